// round 10
// baseline (speedup 1.0000x reference)
#include <cuda_runtime.h>
#include <cuda_bf16.h>
#include <math.h>
#include <stdint.h>

#define WOUT 40
#define HWOUT 1600
#define CIN 256
#define BATCH 4

#define BN 64
#define KC 64
#define NT 256
#define KDEF (CIN*16)
#define KCONV (CIN*9)

#define ND (256*KDEF)
#define NCOM (64*KCONV)
#define NRES (256*KCONV)

// unified smem layout (bytes): A 4 slots x 16KB = 64KB | B 4 x 8KB = 32KB | OM 12KB
#define ABUF 16384
#define OFF_B 65536
#define OFF_OM 98304
#define SMEM_FUSED 110592
#define SMEM_RES 98304

// ---------------- device scratch ----------------
__device__ float g_f[2][BATCH*CIN*HWOUT];
__device__ __align__(16) __nv_bfloat16 g_wdef[2*2*ND];
__device__ __align__(16) __nv_bfloat16 g_wcom[2*2*NCOM];
__device__ __align__(16) __nv_bfloat16 g_wres[2*NRES];

__device__ __forceinline__ uint32_t smem_u32(const void* p) {
    uint32_t a;
    asm("{ .reg .u64 t; cvta.to.shared.u64 t, %1; cvt.u32.u64 %0, t; }" : "=r"(a) : "l"(p));
    return a;
}
__device__ __forceinline__ uint32_t sw128(uint32_t o) { return o ^ ((o >> 3) & 0x70); }

__device__ __forceinline__ void ldsm4(uint32_t* r, uint32_t addr) {
    asm volatile("ldmatrix.sync.aligned.m8n8.x4.shared.b16 {%0,%1,%2,%3}, [%4];"
        : "=r"(r[0]), "=r"(r[1]), "=r"(r[2]), "=r"(r[3]) : "r"(addr));
}
__device__ __forceinline__ void mma16816(float* c, const uint32_t* a, uint32_t b0, uint32_t b1) {
    asm volatile("mma.sync.aligned.m16n8k16.row.col.f32.bf16.bf16.f32 "
        "{%0,%1,%2,%3},{%4,%5,%6,%7},{%8,%9},{%0,%1,%2,%3};"
        : "+f"(c[0]), "+f"(c[1]), "+f"(c[2]), "+f"(c[3])
        : "r"(a[0]), "r"(a[1]), "r"(a[2]), "r"(a[3]), "r"(b0), "r"(b1));
}

// MODE 0: implicit 3x3 conv (s1 p1). MODE 1: modulated deform conv (k=4,K=16), meta from smem om.
// EPI 0:+bias 1:relu(v+b)+epi 2:v+b+epi 3:+bias->som
// 8 warps: wm = wid&1 (2 x MT*16 rows), wn = wid>>1 (4 x 16 cols). BM = MT*32.
template<int MODE, int EPI, int MT>
__device__ void stage_gemm(char* smem, int bxn, int m0,
        const float* __restrict__ x, int Hin, int Win,
        const __nv_bfloat16* __restrict__ whi, const __nv_bfloat16* __restrict__ wlo,
        const float* __restrict__ bias,
        float* som, const float* __restrict__ epi_src, float* __restrict__ out,
        int Cout, int Ktot, int stride, int pad, int dil)
{
    constexpr int BM = MT * 32;
    const uint32_t sb = smem_u32(smem);
    const int tid = threadIdx.x;
    const int wid = tid >> 5, lid = tid & 31;
    const int n0 = bxn * BN;
    const int b  = n0 / HWOUT;
    const int hw0 = n0 - b * HWOUT;
    const int HWin = Hin * Win;
    const float* xb = x + (size_t)b * CIN * HWin;

    __syncthreads();   // previous stage done with smem (incl. som writes)

    const int pxT = tid & 63;
    const int grpT = tid >> 6;            // 0..3
    const uint32_t xorv = (uint32_t)((pxT & 7) << 4);
    const uint32_t rowb = (uint32_t)(pxT * 128);

    // deform meta: 2 tap-pairs (4 taps) per thread, in regs
    int2 ad[2][2]; float4 wq[2][2];
    if (MODE == 1) {
#pragma unroll
        for (int pp = 0; pp < 2; pp++)
#pragma unroll
        for (int u = 0; u < 2; u++) {
            int k = (2 * grpT + pp) * 2 + u;
            int hw = hw0 + pxT;
            int h = hw / WOUT, w = hw - h * WOUT;
            float dy = som[(2*k  ) * 64 + pxT];
            float dx = som[(2*k+1) * 64 + pxT];
            float mm = som[(32+k ) * 64 + pxT];
            mm = 1.0f / (1.0f + expf(-mm));
            float py = (float)((k >> 2) * dil + h * stride - pad) + dy;
            float px = (float)((k &  3) * dil + w * stride - pad) + dx;
            float fy = floorf(py), fx = floorf(px);
            int y0 = (int)fy, x0 = (int)fx;
            int y1 = y0 + 1, x1 = x0 + 1;
            float ly = py - fy, lx = px - fx;
            float wy0 = ((y0 >= 0) & (y0 < Hin)) ? (1.f - ly) * mm : 0.f;
            float wy1 = ((y1 >= 0) & (y1 < Hin)) ? ly * mm : 0.f;
            float wx0 = ((x0 >= 0) & (x0 < Win)) ? (1.f - lx) : 0.f;
            float wx1 = ((x1 >= 0) & (x1 < Win)) ? lx : 0.f;
            int xL = min(max(x0, 0), Win - 2);
            float wL = (x0 == xL ? wx0 : 0.f) + (x1 == xL ? wx1 : 0.f);
            float wR = (x0 == xL + 1 ? wx0 : 0.f) + (x1 == xL + 1 ? wx1 : 0.f);
            int yT = min(max(y0, 0), Hin - 1);
            int yB = min(max(y1, 0), Hin - 1);
            ad[pp][u] = make_int2(yT * Win + xL, (yB - yT) * Win);
            wq[pp][u] = make_float4(wy0 * wL, wy0 * wR, wy1 * wL, wy1 * wR);
        }
    }

    float acc[MT][2][4];
#pragma unroll
    for (int i = 0; i < MT; i++)
#pragma unroll
        for (int j = 0; j < 2; j++)
#pragma unroll
            for (int q = 0; q < 4; q++) acc[i][j][q] = 0.f;

    const int NC = Ktot / KC;
    const int wm = wid & 1, wn = wid >> 1;
    const int m0w = wm * (MT * 16);
    const int n0w = wn * 16;

    auto loadA_async = [&](int c, int buf) {
        const int k0 = c * KC;
        constexpr int TOT = BM * 16;   // 2 fmt x BM x 8 groups
#pragma unroll
        for (int s = 0; s < TOT / NT; s++) {
            int f = tid + s * NT;
            int fmt = f / (BM * 8);
            int rem = f - fmt * (BM * 8);
            int r = rem >> 3, j = rem & 7;
            const __nv_bfloat16* src = fmt ? wlo : whi;
            uint32_t dst = sb + (uint32_t)((buf*2 + fmt) * ABUF) + sw128((uint32_t)(r*128 + j*16));
            const void* gsrc = src + (size_t)(m0 + r) * Ktot + k0 + j * 8;
            asm volatile("cp.async.cg.shared.global [%0], [%1], 16;" :: "r"(dst), "l"(gsrc));
        }
        asm volatile("cp.async.commit_group;");
    };

    auto gatherB_def = [&](int c, int buf) {
#pragma unroll
        for (int ciL = 0; ciL < 4; ciL++) {
            const float* plane = xb + (size_t)(c * 4 + ciL) * HWin;
#pragma unroll
            for (int pp = 0; pp < 2; pp++) {
                const float* p0 = plane + ad[pp][0].x;
                const float* p1 = plane + ad[pp][1].x;
                float v0 = wq[pp][0].x*p0[0] + wq[pp][0].y*p0[1] + wq[pp][0].z*p0[ad[pp][0].y] + wq[pp][0].w*p0[ad[pp][0].y+1];
                float v1 = wq[pp][1].x*p1[0] + wq[pp][1].y*p1[1] + wq[pp][1].z*p1[ad[pp][1].y] + wq[pp][1].w*p1[ad[pp][1].y+1];
                __nv_bfloat162 hh = __floats2bfloat162_rn(v0, v1);
                float l0 = v0 - __bfloat162float(hh.x);
                float l1 = v1 - __bfloat162float(hh.y);
                __nv_bfloat162 ll = __floats2bfloat162_rn(l0, l1);
                uint32_t so = rowb + (((uint32_t)(ciL * 32 + (2*grpT+pp) * 4)) ^ xorv);
                *(uint32_t*)(smem + OFF_B + (buf*2 + 0) * 8192 + so) = *(uint32_t*)&hh;
                *(uint32_t*)(smem + OFF_B + (buf*2 + 1) * 8192 + so) = *(uint32_t*)&ll;
            }
        }
    };

    auto gatherB_conv = [&](int c, int buf) {
        int hw = hw0 + pxT;
        int h = hw / WOUT, w_ = hw - h * WOUT;
#pragma unroll
        for (int q = 0; q < 8; q++) {
            float v[2];
#pragma unroll
            for (int u = 0; u < 2; u++) {
                int k = c * KC + grpT * 16 + q * 2 + u;
                int ci = k / 9, jj = k - ci * 9;
                int y  = h + jj / 3 - 1;
                int xx = w_ + (jj - (jj / 3) * 3) - 1;
                v[u] = (y >= 0 && y < Hin && xx >= 0 && xx < Win)
                     ? xb[(size_t)ci * HWin + y * Win + xx] : 0.f;
            }
            __nv_bfloat162 hh = __floats2bfloat162_rn(v[0], v[1]);
            float l0 = v[0] - __bfloat162float(hh.x);
            float l1 = v[1] - __bfloat162float(hh.y);
            __nv_bfloat162 ll = __floats2bfloat162_rn(l0, l1);
            uint32_t so = rowb + (((uint32_t)(grpT * 32 + q * 4)) ^ xorv);
            *(uint32_t*)(smem + OFF_B + (buf*2 + 0) * 8192 + so) = *(uint32_t*)&hh;
            *(uint32_t*)(smem + OFF_B + (buf*2 + 1) * 8192 + so) = *(uint32_t*)&ll;
        }
    };

    const uint32_t aOff = (uint32_t)((m0w + (lid & 15)) * 128 + (lid >> 4) * 16);
    const uint32_t bOff = (uint32_t)((n0w + (lid & 7) + ((lid >> 4) & 1) * 8) * 128 + ((lid >> 3) & 1) * 16);

    loadA_async(0, 0);
    if (MODE == 1) gatherB_def(0, 0); else gatherB_conv(0, 0);
    asm volatile("cp.async.wait_group 0;");
    __syncthreads();

    for (int c = 0; c < NC; c++) {
        const int buf = c & 1;
        if (c + 1 < NC) {
            loadA_async(c + 1, buf ^ 1);
            if (MODE == 1) gatherB_def(c + 1, buf ^ 1); else gatherB_conv(c + 1, buf ^ 1);
        }

        const uint32_t sAh = sb + (uint32_t)((buf*2 + 0) * ABUF);
        const uint32_t sAl = sb + (uint32_t)((buf*2 + 1) * ABUF);
        const uint32_t sBh = sb + OFF_B + (buf*2 + 0) * 8192;
        const uint32_t sBl = sb + OFF_B + (buf*2 + 1) * 8192;

#pragma unroll
        for (int ks = 0; ks < 4; ks++) {
            uint32_t ah[MT][4], al[MT][4], bh[4], bl[4];
#pragma unroll
            for (int i = 0; i < MT; i++) {
                ldsm4(ah[i], sAh + sw128(aOff + (uint32_t)(i * 2048 + ks * 32)));
                ldsm4(al[i], sAl + sw128(aOff + (uint32_t)(i * 2048 + ks * 32)));
            }
            ldsm4(bh, sBh + sw128(bOff + (uint32_t)(ks * 32)));
            ldsm4(bl, sBl + sw128(bOff + (uint32_t)(ks * 32)));
#pragma unroll
            for (int i = 0; i < MT; i++)
#pragma unroll
                for (int jn = 0; jn < 2; jn++) {
                    int sel = jn * 2;
                    mma16816(acc[i][jn], ah[i], bh[sel], bh[sel + 1]);
                    mma16816(acc[i][jn], ah[i], bl[sel], bl[sel + 1]);
                    mma16816(acc[i][jn], al[i], bh[sel], bh[sel + 1]);
                }
        }
        if (c + 1 < NC) asm volatile("cp.async.wait_group 0;");
        __syncthreads();
    }

    // ---- epilogue ----
#pragma unroll
    for (int i = 0; i < MT; i++) {
        int rowl = m0w + i * 16 + (lid >> 2);
#pragma unroll
        for (int half = 0; half < 2; half++) {
            int col = rowl + half * 8;       // local row within BM
            int co = m0 + col;
            if (col >= BM || co >= Cout) continue;
            float bv = bias[co];
#pragma unroll
            for (int jn = 0; jn < 2; jn++) {
                float v0 = acc[i][jn][half * 2 + 0] + bv;
                float v1 = acc[i][jn][half * 2 + 1] + bv;
                if (EPI == 3) {
                    int cb = co * 64 + n0w + (lid & 3) * 2 + jn * 8;
                    som[cb] = v0; som[cb + 1] = v1;
                } else {
                    size_t o = ((size_t)b * Cout + co) * HWOUT + hw0 + n0w + (lid & 3) * 2 + jn * 8;
                    if (EPI == 1) {
                        float2 s = *(const float2*)(epi_src + o);
                        v0 = fmaxf(v0, 0.f) + s.x; v1 = fmaxf(v1, 0.f) + s.y;
                    } else if (EPI == 2) {
                        float2 s = *(const float2*)(epi_src + o);
                        v0 += s.x; v1 += s.y;
                    }
                    *(float2*)(out + o) = make_float2(v0, v1);
                }
            }
        }
    }
}

// fused per-level kernel: com (dup per m-half) -> deform
__global__ void __launch_bounds__(NT, 2)
level_kernel(const float* __restrict__ feat, int Hin,
             const float* __restrict__ gfr, float* __restrict__ gfw,
             const __nv_bfloat16* wc, const float* __restrict__ cbias,
             const __nv_bfloat16* wd, const float* __restrict__ dbias,
             int stride, int pad, int dil)
{
    extern __shared__ __align__(1024) char smem[];
    const int bxn = blockIdx.x % 100;
    const int m0 = (blockIdx.x / 100) * 128;
    float* som = (float*)(smem + OFF_OM);

    stage_gemm<0,3,2>(smem, bxn, 0, gfr, 40, 40, wc, wc + NCOM,
                      cbias, som, nullptr, nullptr, 48, KCONV, 1, 1, 1);
    stage_gemm<1,1,4>(smem, bxn, m0, feat, Hin, Hin, wd, wd + ND,
                      dbias, som, gfr, gfw, 256, KDEF, stride, pad, dil);
}

__global__ void __launch_bounds__(NT, 2)
res_kernel(const float* __restrict__ gfr, const float* __restrict__ f2,
           const float* __restrict__ rbias, float* __restrict__ out)
{
    extern __shared__ __align__(1024) char smem[];
    const int bxn = blockIdx.x % 100;
    const int m0 = (blockIdx.x / 100) * 128;
    stage_gemm<0,2,4>(smem, bxn, m0, gfr, 40, 40, g_wres, g_wres + NRES,
                      rbias, nullptr, f2, out, 256, KCONV, 1, 1, 1);
}

__global__ void prep_kernel(const float* dw0, const float* dw1,
                            const float* cw0, const float* cw1, const float* rw)
{
    const int gtid = blockIdx.x * blockDim.x + threadIdx.x;
    const int GT = gridDim.x * blockDim.x;
    const float* dsrc[2] = {dw0, dw1};
    for (int l = 0; l < 2; l++) {
        __nv_bfloat16* hi = g_wdef + (size_t)l * 2 * ND;
        for (int i = gtid; i < ND; i += GT) {
            float v = dsrc[l][i];
            __nv_bfloat16 h = __float2bfloat16(v);
            hi[i] = h; hi[ND + i] = __float2bfloat16(v - __bfloat162float(h));
        }
    }
    const float* csrc[2] = {cw0, cw1};
    for (int l = 0; l < 2; l++) {
        __nv_bfloat16* hi = g_wcom + (size_t)l * 2 * NCOM;
        for (int i = gtid; i < NCOM; i += GT) {
            int row = i / KCONV;
            float v = (row < 48) ? csrc[l][i] : 0.f;
            __nv_bfloat16 h = __float2bfloat16(v);
            hi[i] = h; hi[NCOM + i] = __float2bfloat16(v - __bfloat162float(h));
        }
    }
    for (int i = gtid; i < NRES; i += GT) {
        float v = rw[i];
        __nv_bfloat16 h = __float2bfloat16(v);
        g_wres[i] = h; g_wres[NRES + i] = __float2bfloat16(v - __bfloat162float(h));
    }
}

extern "C" void kernel_launch(void* const* d_in, const int* in_sizes, int n_in,
                              void* d_out, int out_size)
{
    const float* f0 = (const float*)d_in[0];
    const float* f1 = (const float*)d_in[1];
    const float* f2 = (const float*)d_in[2];
    const float* cb[2] = {(const float*)d_in[4], (const float*)d_in[6]};
    const float* db[2] = {(const float*)d_in[8], (const float*)d_in[10]};
    const float* rb = (const float*)d_in[12];

    float* gf;
    cudaGetSymbolAddress((void**)&gf, g_f);
    float* gfb[2] = {gf, gf + BATCH*CIN*HWOUT};

    cudaFuncSetAttribute(level_kernel, cudaFuncAttributeMaxDynamicSharedMemorySize, SMEM_FUSED);
    cudaFuncSetAttribute(res_kernel,   cudaFuncAttributeMaxDynamicSharedMemorySize, SMEM_RES);

    prep_kernel<<<148, 256>>>((const float*)d_in[7], (const float*)d_in[9],
                              (const float*)d_in[3], (const float*)d_in[5],
                              (const float*)d_in[11]);
    cudaMemcpyAsync(gfb[0], f2, sizeof(float) * BATCH * CIN * HWOUT, cudaMemcpyDeviceToDevice);

    __nv_bfloat16 *wdef, *wcom;
    cudaGetSymbolAddress((void**)&wdef, g_wdef);
    cudaGetSymbolAddress((void**)&wcom, g_wcom);

    const float* feats[2] = {f1, f0};
    const int Hins[2] = {80, 160};
    const int strides[2] = {2, 4};
    const int pads[2] = {1, 3};
    const int dils[2] = {1, 3};

    for (int L = 0; L < 4; L++) {
        int l = L & 1;
        level_kernel<<<200, NT, SMEM_FUSED>>>(
            feats[l], Hins[l], gfb[L & 1 ? 1 : 0], gfb[L & 1 ? 0 : 1],
            wcom + (size_t)l*2*NCOM, cb[l],
            wdef + (size_t)l*2*ND, db[l],
            strides[l], pads[l], dils[l]);
    }
    // L0: r0 w1, L1: r1 w0, L2: r0 w1, L3: r1 w0 -> final state in gfb[0]
    res_kernel<<<200, NT, SMEM_RES>>>(gfb[0], f2, rb, (float*)d_out);
}

// round 12
// speedup vs baseline: 1.2876x; 1.2876x over previous
#include <cuda_runtime.h>
#include <cuda_bf16.h>
#include <math.h>
#include <stdint.h>

#define WOUT 40
#define HWOUT 1600
#define CIN 256
#define BATCH 4

#define BN 64
#define KC 64
#define NTHREADS 512
#define GRID 100
#define KDEF (CIN*16)
#define KCONV (CIN*9)

#define ND (256*KDEF)
#define NCOM (64*KCONV)
#define NRES (256*KCONV)

// smem (bytes): A [0,131072) B [131072,163840) OM [163840,176128)
#define OFF_OM 163840
#define SMEM_TOTAL 176128

__device__ float g_f[BATCH*CIN*HWOUT];
__device__ __align__(16) __nv_bfloat16 g_wdef[2*2*ND];
__device__ __align__(16) __nv_bfloat16 g_wcom[2*2*NCOM];
__device__ __align__(16) __nv_bfloat16 g_wres[2*NRES];
__device__ unsigned int g_cnt[8];

__device__ __forceinline__ uint32_t smem_u32(const void* p) {
    uint32_t a;
    asm("{ .reg .u64 t; cvta.to.shared.u64 t, %1; cvt.u32.u64 %0, t; }" : "=r"(a) : "l"(p));
    return a;
}
__device__ __forceinline__ uint32_t sw128(uint32_t o) { return o ^ ((o >> 3) & 0x70); }

__device__ __forceinline__ void ldsm4(uint32_t* r, uint32_t addr) {
    asm volatile("ldmatrix.sync.aligned.m8n8.x4.shared.b16 {%0,%1,%2,%3}, [%4];"
        : "=r"(r[0]), "=r"(r[1]), "=r"(r[2]), "=r"(r[3]) : "r"(addr));
}
__device__ __forceinline__ void mma16816(float* c, const uint32_t* a, uint32_t b0, uint32_t b1) {
    asm volatile("mma.sync.aligned.m16n8k16.row.col.f32.bf16.bf16.f32 "
        "{%0,%1,%2,%3},{%4,%5,%6,%7},{%8,%9},{%0,%1,%2,%3};"
        : "+f"(c[0]), "+f"(c[1]), "+f"(c[2]), "+f"(c[3])
        : "r"(a[0]), "r"(a[1]), "r"(a[2]), "r"(a[3]), "r"(b0), "r"(b1));
}

// monotone-counter grid barrier (graph-replay safe)
__device__ __forceinline__ void grid_bar(int slot) {
    __syncthreads();
    if (threadIdx.x == 0) {
        __threadfence();
        unsigned int old = atomicAdd(&g_cnt[slot], 1u);
        unsigned int target = (old / GRID) * GRID + GRID;
        while (*(volatile unsigned int*)&g_cnt[slot] < target) __nanosleep(64);
    }
    __syncthreads();
}

// MODE 0: implicit 3x3 conv (s1 p1; x = mutable gf, read via __ldcg).
// MODE 1: modulated deform conv (k=4,K=16), meta from smem om; x = immutable feat.
// EPI 0:+bias 1:relu(v+b)+__ldcg(epi) 2:v+b+__ldcg(epi) 3:+bias->som
template<int MODE, int EPI, int MT>
__device__ void stage_gemm(char* smem, int bx,
        const float* __restrict__ x, int Hin, int Win,
        const __nv_bfloat16* __restrict__ whi, const __nv_bfloat16* __restrict__ wlo,
        const float* __restrict__ bias,
        float* som, const float* __restrict__ epi_src, float* __restrict__ out,
        int Cout, int Ktot, int stride, int pad, int dil)
{
    constexpr int BM = MT * 64;
    constexpr int ABUF = BM * 128;
    constexpr int OFF_B = 4 * ABUF;

    const uint32_t sb = smem_u32(smem);
    const int tid = threadIdx.x;
    const int wid = tid >> 5, lid = tid & 31;
    const int n0 = bx * BN;
    const int b  = n0 / HWOUT;
    const int hw0 = n0 - b * HWOUT;
    const int HWin = Hin * Win;
    const float* xb = x + (size_t)b * CIN * HWin;

    __syncthreads();   // previous stage fully done with smem

    const int pxT = tid & 63;
    const int grpT = tid >> 6;
    const uint32_t xorv = (uint32_t)((pxT & 7) << 4);
    const uint32_t rowb = (uint32_t)(pxT * 128);

    // ---- per-thread deform meta (tap pair) from smem om, held in regs ----
    int2 ad[2]; float4 wq[2];
    if (MODE == 1) {
#pragma unroll
        for (int u = 0; u < 2; u++) {
            int k = 2 * grpT + u;
            int hw = hw0 + pxT;
            int h = hw / WOUT, w = hw - h * WOUT;
            float dy = som[(2*k  ) * 64 + pxT];
            float dx = som[(2*k+1) * 64 + pxT];
            float mm = som[(32+k ) * 64 + pxT];
            mm = 1.0f / (1.0f + expf(-mm));
            float py = (float)((k >> 2) * dil + h * stride - pad) + dy;
            float px = (float)((k &  3) * dil + w * stride - pad) + dx;
            float fy = floorf(py), fx = floorf(px);
            int y0 = (int)fy, x0 = (int)fx;
            int y1 = y0 + 1, x1 = x0 + 1;
            float ly = py - fy, lx = px - fx;
            float wy0 = ((y0 >= 0) & (y0 < Hin)) ? (1.f - ly) * mm : 0.f;
            float wy1 = ((y1 >= 0) & (y1 < Hin)) ? ly * mm : 0.f;
            float wx0 = ((x0 >= 0) & (x0 < Win)) ? (1.f - lx) : 0.f;
            float wx1 = ((x1 >= 0) & (x1 < Win)) ? lx : 0.f;
            int xL = min(max(x0, 0), Win - 2);
            float wL = (x0 == xL ? wx0 : 0.f) + (x1 == xL ? wx1 : 0.f);
            float wR = (x0 == xL + 1 ? wx0 : 0.f) + (x1 == xL + 1 ? wx1 : 0.f);
            int yT = min(max(y0, 0), Hin - 1);
            int yB = min(max(y1, 0), Hin - 1);
            ad[u] = make_int2(yT * Win + xL, (yB - yT) * Win);
            wq[u] = make_float4(wy0 * wL, wy0 * wR, wy1 * wL, wy1 * wR);
        }
    }

    float acc[MT][2][4];
#pragma unroll
    for (int i = 0; i < MT; i++)
#pragma unroll
        for (int j = 0; j < 2; j++)
#pragma unroll
            for (int q = 0; q < 4; q++) acc[i][j][q] = 0.f;

    const int NC = Ktot / KC;
    const int wm = wid & 3, wn = wid >> 2;
    const int m0w = wm * (MT * 16);
    const int n0w = wn * 16;

    auto loadA_async = [&](int c, int buf) {
        const int k0 = c * KC;
        constexpr int TOT = BM * 16;
#pragma unroll
        for (int s = 0; s < TOT / NTHREADS; s++) {
            int f = tid + s * NTHREADS;
            int fmt = f / (BM * 8);
            int rem = f - fmt * (BM * 8);
            int r = rem >> 3, j = rem & 7;
            const __nv_bfloat16* src = fmt ? wlo : whi;
            uint32_t dst = sb + (uint32_t)((buf*2 + fmt) * ABUF) + sw128((uint32_t)(r*128 + j*16));
            const void* gsrc = src + (size_t)r * Ktot + k0 + j * 8;
            asm volatile("cp.async.cg.shared.global [%0], [%1], 16;" :: "r"(dst), "l"(gsrc));
        }
        asm volatile("cp.async.commit_group;");
    };

    // ---- deform gather, quarter granularity: 1 channel (ciL=q), 8 LDG -> r8 ----
    auto ldg_q = [&](int c, int q, float* r8) {
        const float* plane = xb + (size_t)(c * 4 + q) * HWin;
#pragma unroll
        for (int u = 0; u < 2; u++) {
            const float* p = plane + ad[u].x;
            r8[u*4+0] = p[0];
            r8[u*4+1] = p[1];
            r8[u*4+2] = p[ad[u].y];
            r8[u*4+3] = p[ad[u].y+1];
        }
    };
    auto sts_q = [&](int q, int buf, const float* r8) {
        float v0 = wq[0].x*r8[0] + wq[0].y*r8[1] + wq[0].z*r8[2] + wq[0].w*r8[3];
        float v1 = wq[1].x*r8[4] + wq[1].y*r8[5] + wq[1].z*r8[6] + wq[1].w*r8[7];
        __nv_bfloat162 hh = __floats2bfloat162_rn(v0, v1);
        float l0 = v0 - __bfloat162float(hh.x);
        float l1 = v1 - __bfloat162float(hh.y);
        __nv_bfloat162 ll = __floats2bfloat162_rn(l0, l1);
        uint32_t so = rowb + (((uint32_t)(q * 32 + grpT * 4)) ^ xorv);
        *(uint32_t*)(smem + OFF_B + (buf*2 + 0) * 8192 + so) = *(uint32_t*)&hh;
        *(uint32_t*)(smem + OFF_B + (buf*2 + 1) * 8192 + so) = *(uint32_t*)&ll;
    };

    auto gatherB_conv = [&](int c, int buf) {
        int hw = hw0 + pxT;
        int h = hw / WOUT, w_ = hw - h * WOUT;
#pragma unroll
        for (int q = 0; q < 4; q++) {
            float v[2];
#pragma unroll
            for (int u = 0; u < 2; u++) {
                int k = c * KC + grpT * 8 + q * 2 + u;
                int ci = k / 9, jj = k - ci * 9;
                int y  = h + jj / 3 - 1;
                int xx = w_ + (jj - (jj / 3) * 3) - 1;
                v[u] = (y >= 0 && y < Hin && xx >= 0 && xx < Win)
                     ? __ldcg(&xb[(size_t)ci * HWin + y * Win + xx]) : 0.f;
            }
            __nv_bfloat162 hh = __floats2bfloat162_rn(v[0], v[1]);
            float l0 = v[0] - __bfloat162float(hh.x);
            float l1 = v[1] - __bfloat162float(hh.y);
            __nv_bfloat162 ll = __floats2bfloat162_rn(l0, l1);
            uint32_t so = rowb + (((uint32_t)(grpT * 16 + q * 4)) ^ xorv);
            *(uint32_t*)(smem + OFF_B + (buf*2 + 0) * 8192 + so) = *(uint32_t*)&hh;
            *(uint32_t*)(smem + OFF_B + (buf*2 + 1) * 8192 + so) = *(uint32_t*)&ll;
        }
    };

    const uint32_t aOff = (uint32_t)((m0w + (lid & 15)) * 128 + (lid >> 4) * 16);
    const uint32_t bOff = (uint32_t)((n0w + (lid & 7) + ((lid >> 4) & 1) * 8) * 128 + ((lid >> 3) & 1) * 16);

    // one ks-group of MMAs on buffer `buf`
    auto mma_ks = [&](int buf, int ks) {
        const uint32_t sAh = sb + (uint32_t)((buf*2 + 0) * ABUF);
        const uint32_t sAl = sb + (uint32_t)((buf*2 + 1) * ABUF);
        const uint32_t sBh = sb + OFF_B + (buf*2 + 0) * 8192;
        const uint32_t sBl = sb + OFF_B + (buf*2 + 1) * 8192;
        uint32_t bh[4], bl[4];
        ldsm4(bh, sBh + sw128(bOff + (uint32_t)(ks * 32)));
        ldsm4(bl, sBl + sw128(bOff + (uint32_t)(ks * 32)));
#pragma unroll
        for (int i = 0; i < MT; i++) {
            uint32_t ah[4], al[4];
            ldsm4(ah, sAh + sw128(aOff + (uint32_t)(i * 2048 + ks * 32)));
            ldsm4(al, sAl + sw128(aOff + (uint32_t)(i * 2048 + ks * 32)));
#pragma unroll
            for (int jn = 0; jn < 2; jn++) {
                int sel = jn * 2;
                mma16816(acc[i][jn], ah, bh[sel], bh[sel + 1]);
                mma16816(acc[i][jn], ah, bl[sel], bl[sel + 1]);
                mma16816(acc[i][jn], al, bh[sel], bh[sel + 1]);
            }
        }
    };

    // ---- prologue: chunk 0 ----
    loadA_async(0, 0);
    if (MODE == 1) {
        float r8[8];
#pragma unroll
        for (int q = 0; q < 4; q++) { ldg_q(0, q, r8); sts_q(q, 0, r8); }
    } else {
        gatherB_conv(0, 0);
    }
    asm volatile("cp.async.wait_group 0;");
    __syncthreads();

    // ---- mainloop ----
    if (MODE == 1) {
        float r0[8], r1[8];
        for (int c = 0; c < NC; c++) {
            const int buf = c & 1;
            const bool nxt = (c + 1 < NC);
            if (nxt) {
                loadA_async(c + 1, buf ^ 1);
                ldg_q(c + 1, 0, r0);
                ldg_q(c + 1, 1, r1);
            }
            mma_ks(buf, 0);
            if (nxt) { sts_q(0, buf ^ 1, r0); ldg_q(c + 1, 2, r0); }
            mma_ks(buf, 1);
            if (nxt) { sts_q(1, buf ^ 1, r1); ldg_q(c + 1, 3, r1); }
            mma_ks(buf, 2);
            if (nxt) sts_q(2, buf ^ 1, r0);
            mma_ks(buf, 3);
            if (nxt) {
                sts_q(3, buf ^ 1, r1);
                asm volatile("cp.async.wait_group 0;");
            }
            __syncthreads();
        }
    } else {
        for (int c = 0; c < NC; c++) {
            const int buf = c & 1;
            const bool nxt = (c + 1 < NC);
            if (nxt) {
                loadA_async(c + 1, buf ^ 1);
                gatherB_conv(c + 1, buf ^ 1);
            }
#pragma unroll
            for (int ks = 0; ks < 4; ks++) mma_ks(buf, ks);
            if (nxt) asm volatile("cp.async.wait_group 0;");
            __syncthreads();
        }
    }

    // ---- epilogue ----
#pragma unroll
    for (int i = 0; i < MT; i++) {
        int row0 = m0w + i * 16 + (lid >> 2);
#pragma unroll
        for (int half = 0; half < 2; half++) {
            int co = row0 + half * 8;
            if (co >= Cout) continue;
            float bv = bias[co];
#pragma unroll
            for (int jn = 0; jn < 2; jn++) {
                float v0 = acc[i][jn][half * 2 + 0] + bv;
                float v1 = acc[i][jn][half * 2 + 1] + bv;
                if (EPI == 3) {
                    int cb = co * 64 + n0w + (lid & 3) * 2 + jn * 8;
                    som[cb] = v0; som[cb + 1] = v1;
                } else {
                    size_t o = ((size_t)b * Cout + co) * HWOUT + hw0 + n0w + (lid & 3) * 2 + jn * 8;
                    if (EPI == 1) {
                        float2 s = __ldcg((const float2*)(epi_src + o));
                        v0 = fmaxf(v0, 0.f) + s.x; v1 = fmaxf(v1, 0.f) + s.y;
                    } else if (EPI == 2) {
                        float2 s = __ldcg((const float2*)(epi_src + o));
                        v0 += s.x; v1 += s.y;
                    }
                    *(float2*)(out + o) = make_float2(v0, v1);
                }
            }
        }
    }
}

__global__ void __launch_bounds__(NTHREADS)
dcnfpn_persist(const float* __restrict__ f0, const float* __restrict__ f1,
               const float* __restrict__ f2,
               const float* cw0, const float* cb0, const float* cw1, const float* cb1,
               const float* dw0, const float* db0, const float* dw1, const float* db1,
               const float* rw, const float* rb, float* __restrict__ out)
{
    extern __shared__ __align__(1024) char smem[];
    const int bx = blockIdx.x;
    const int tid = threadIdx.x;
    const int gtid = bx * NTHREADS + tid;
    const int GT = GRID * NTHREADS;

    // ---- prep: weights fp32 -> bf16 hi/lo; gf = f2 ----
    {
        const float* dsrc[2] = {dw0, dw1};
        for (int l = 0; l < 2; l++) {
            __nv_bfloat16* hi = g_wdef + (size_t)l * 2 * ND;
            __nv_bfloat16* lo = hi + ND;
            for (int i = gtid; i < ND; i += GT) {
                float v = dsrc[l][i];
                __nv_bfloat16 h = __float2bfloat16(v);
                hi[i] = h; lo[i] = __float2bfloat16(v - __bfloat162float(h));
            }
        }
        const float* csrc[2] = {cw0, cw1};
        for (int l = 0; l < 2; l++) {
            __nv_bfloat16* hi = g_wcom + (size_t)l * 2 * NCOM;
            __nv_bfloat16* lo = hi + NCOM;
            for (int i = gtid; i < NCOM; i += GT) {
                int row = i / KCONV;
                float v = (row < 48) ? csrc[l][i] : 0.f;
                __nv_bfloat16 h = __float2bfloat16(v);
                hi[i] = h; lo[i] = __float2bfloat16(v - __bfloat162float(h));
            }
        }
        for (int i = gtid; i < NRES; i += GT) {
            float v = rw[i];
            __nv_bfloat16 h = __float2bfloat16(v);
            g_wres[i] = h; g_wres[NRES + i] = __float2bfloat16(v - __bfloat162float(h));
        }
        const float4* s4 = (const float4*)f2;
        float4* d4 = (float4*)g_f;
        for (int i = gtid; i < BATCH*CIN*HWOUT/4; i += GT) d4[i] = s4[i];
    }
    grid_bar(0);

    float* som = (float*)(smem + OFF_OM);
    const float* feats[2] = {f1, f0};
    const float* cb[2] = {cb0, cb1};
    const float* db[2] = {db0, db1};
    const int Hins[2] = {80, 160};
    const int strides[2] = {2, 4};
    const int pads[2] = {1, 3};
    const int dils[2] = {1, 3};

    int slot = 1;
    for (int rep = 0; rep < 2; rep++) {
        for (int l = 0; l < 2; l++) {
            stage_gemm<0,3,1>(smem, bx, g_f, 40, 40,
                g_wcom + (size_t)l*2*NCOM, g_wcom + (size_t)l*2*NCOM + NCOM,
                cb[l], som, nullptr, nullptr, 48, KCONV, 1, 1, 1);
            stage_gemm<1,1,4>(smem, bx, feats[l], Hins[l], Hins[l],
                g_wdef + (size_t)l*2*ND, g_wdef + (size_t)l*2*ND + ND,
                db[l], som, g_f, g_f, 256, KDEF, strides[l], pads[l], dils[l]);
            grid_bar(slot++);
        }
    }
    stage_gemm<0,2,4>(smem, bx, g_f, 40, 40,
        g_wres, g_wres + NRES, rb, nullptr, f2, out, 256, KCONV, 1, 1, 1);
}

extern "C" void kernel_launch(void* const* d_in, const int* in_sizes, int n_in,
                              void* d_out, int out_size)
{
    const float* f0 = (const float*)d_in[0];
    const float* f1 = (const float*)d_in[1];
    const float* f2 = (const float*)d_in[2];

    cudaFuncSetAttribute(dcnfpn_persist, cudaFuncAttributeMaxDynamicSharedMemorySize, SMEM_TOTAL);

    dcnfpn_persist<<<GRID, NTHREADS, SMEM_TOTAL>>>(
        f0, f1, f2,
        (const float*)d_in[3], (const float*)d_in[4],
        (const float*)d_in[5], (const float*)d_in[6],
        (const float*)d_in[7], (const float*)d_in[8],
        (const float*)d_in[9], (const float*)d_in[10],
        (const float*)d_in[11], (const float*)d_in[12],
        (float*)d_out);
}

// round 14
// speedup vs baseline: 1.3162x; 1.0222x over previous
#include <cuda_runtime.h>
#include <cuda_bf16.h>
#include <math.h>
#include <stdint.h>

#define WOUT 40
#define HWOUT 1600
#define CIN 256
#define BATCH 4

#define BN 64
#define KC 64
#define NTHREADS 512
#define GRID 100
#define KDEF (CIN*16)
#define KCONV (CIN*9)

#define ND (256*KDEF)
#define NCOM (64*KCONV)
#define NRES (256*KCONV)

// smem (bytes): A [0,131072) B [131072,163840) OM [163840,176128)
#define OFF_OM 163840
#define SMEM_TOTAL 176128

__device__ float g_f[BATCH*CIN*HWOUT];
__device__ __align__(16) __nv_bfloat16 g_wdef[2*2*ND];
__device__ __align__(16) __nv_bfloat16 g_wcom[2*2*NCOM];
__device__ __align__(16) __nv_bfloat16 g_wres[2*NRES];
__device__ unsigned int g_cnt[8];

__device__ __forceinline__ uint32_t smem_u32(const void* p) {
    uint32_t a;
    asm("{ .reg .u64 t; cvta.to.shared.u64 t, %1; cvt.u32.u64 %0, t; }" : "=r"(a) : "l"(p));
    return a;
}
__device__ __forceinline__ uint32_t sw128(uint32_t o) { return o ^ ((o >> 3) & 0x70); }

__device__ __forceinline__ void ldsm4(uint32_t* r, uint32_t addr) {
    asm volatile("ldmatrix.sync.aligned.m8n8.x4.shared.b16 {%0,%1,%2,%3}, [%4];"
        : "=r"(r[0]), "=r"(r[1]), "=r"(r[2]), "=r"(r[3]) : "r"(addr));
}
__device__ __forceinline__ void mma16816(float* c, const uint32_t* a, uint32_t b0, uint32_t b1) {
    asm volatile("mma.sync.aligned.m16n8k16.row.col.f32.bf16.bf16.f32 "
        "{%0,%1,%2,%3},{%4,%5,%6,%7},{%8,%9},{%0,%1,%2,%3};"
        : "+f"(c[0]), "+f"(c[1]), "+f"(c[2]), "+f"(c[3])
        : "r"(a[0]), "r"(a[1]), "r"(a[2]), "r"(a[3]), "r"(b0), "r"(b1));
}

// monotone-counter grid barrier (graph-replay safe)
__device__ __forceinline__ void grid_bar(int slot) {
    __syncthreads();
    if (threadIdx.x == 0) {
        __threadfence();
        unsigned int old = atomicAdd(&g_cnt[slot], 1u);
        unsigned int target = (old / GRID) * GRID + GRID;
        while (*(volatile unsigned int*)&g_cnt[slot] < target) __nanosleep(64);
    }
    __syncthreads();
}

// MODE 0: implicit 3x3 conv (s1 p1; x = mutable gf, read via __ldcg).
// MODE 1: modulated deform conv (k=4,K=16), meta from smem om; x = immutable feat.
// EPI 0:+bias 1:relu(v+b)+__ldcg(epi) 2:v+b+__ldcg(epi) 3:+bias->som
template<int MODE, int EPI, int MT>
__device__ void stage_gemm(char* smem, int bx,
        const float* __restrict__ x, int Hin, int Win,
        const __nv_bfloat16* __restrict__ whi, const __nv_bfloat16* __restrict__ wlo,
        const float* __restrict__ bias,
        float* som, const float* __restrict__ epi_src, float* __restrict__ out,
        int Cout, int Ktot, int stride, int pad, int dil)
{
    constexpr int BM = MT * 64;
    constexpr int ABUF = BM * 128;
    constexpr int OFF_B = 4 * ABUF;

    const uint32_t sb = smem_u32(smem);
    const int tid = threadIdx.x;
    const int wid = tid >> 5, lid = tid & 31;
    const int n0 = bx * BN;
    const int b  = n0 / HWOUT;
    const int hw0 = n0 - b * HWOUT;
    const int HWin = Hin * Win;
    const float* xb = x + (size_t)b * CIN * HWin;

    __syncthreads();   // previous stage fully done with smem

    const int pxT = tid & 63;
    const int grpT = tid >> 6;
    const uint32_t xorv = (uint32_t)((pxT & 7) << 4);
    const uint32_t rowb = (uint32_t)(pxT * 128);

    // ---- per-thread deform meta (tap pair) from smem om, held in regs ----
    int2 ad[2]; float4 wq[2];
    if (MODE == 1) {
#pragma unroll
        for (int u = 0; u < 2; u++) {
            int k = 2 * grpT + u;
            int hw = hw0 + pxT;
            int h = hw / WOUT, w = hw - h * WOUT;
            float dy = som[(2*k  ) * 64 + pxT];
            float dx = som[(2*k+1) * 64 + pxT];
            float mm = som[(32+k ) * 64 + pxT];
            mm = 1.0f / (1.0f + expf(-mm));
            float py = (float)((k >> 2) * dil + h * stride - pad) + dy;
            float px = (float)((k &  3) * dil + w * stride - pad) + dx;
            float fy = floorf(py), fx = floorf(px);
            int y0 = (int)fy, x0 = (int)fx;
            int y1 = y0 + 1, x1 = x0 + 1;
            float ly = py - fy, lx = px - fx;
            float wy0 = ((y0 >= 0) & (y0 < Hin)) ? (1.f - ly) * mm : 0.f;
            float wy1 = ((y1 >= 0) & (y1 < Hin)) ? ly * mm : 0.f;
            float wx0 = ((x0 >= 0) & (x0 < Win)) ? (1.f - lx) : 0.f;
            float wx1 = ((x1 >= 0) & (x1 < Win)) ? lx : 0.f;
            int xL = min(max(x0, 0), Win - 2);
            float wL = (x0 == xL ? wx0 : 0.f) + (x1 == xL ? wx1 : 0.f);
            float wR = (x0 == xL + 1 ? wx0 : 0.f) + (x1 == xL + 1 ? wx1 : 0.f);
            int yT = min(max(y0, 0), Hin - 1);
            int yB = min(max(y1, 0), Hin - 1);
            ad[u] = make_int2(yT * Win + xL, (yB - yT) * Win);
            wq[u] = make_float4(wy0 * wL, wy0 * wR, wy1 * wL, wy1 * wR);
        }
    }

    float acc[MT][2][4];
#pragma unroll
    for (int i = 0; i < MT; i++)
#pragma unroll
        for (int j = 0; j < 2; j++)
#pragma unroll
            for (int q = 0; q < 4; q++) acc[i][j][q] = 0.f;

    const int NC = Ktot / KC;
    const int wm = wid & 3, wn = wid >> 2;
    const int m0w = wm * (MT * 16);
    const int n0w = wn * 16;

    auto loadA_async = [&](int c, int buf) {
        const int k0 = c * KC;
        constexpr int TOT = BM * 16;
#pragma unroll
        for (int s = 0; s < TOT / NTHREADS; s++) {
            int f = tid + s * NTHREADS;
            int fmt = f / (BM * 8);
            int rem = f - fmt * (BM * 8);
            int r = rem >> 3, j = rem & 7;
            const __nv_bfloat16* src = fmt ? wlo : whi;
            uint32_t dst = sb + (uint32_t)((buf*2 + fmt) * ABUF) + sw128((uint32_t)(r*128 + j*16));
            const void* gsrc = src + (size_t)r * Ktot + k0 + j * 8;
            asm volatile("cp.async.cg.shared.global [%0], [%1], 16;" :: "r"(dst), "l"(gsrc));
        }
        asm volatile("cp.async.commit_group;");
    };

    // ---- deform gather, quarter granularity: 1 channel (ciL=q), 8 LDG -> r8 ----
    auto ldg_q = [&](int c, int q, float* r8) {
        const float* plane = xb + (size_t)(c * 4 + q) * HWin;
#pragma unroll
        for (int u = 0; u < 2; u++) {
            const float* p = plane + ad[u].x;
            r8[u*4+0] = p[0];
            r8[u*4+1] = p[1];
            r8[u*4+2] = p[ad[u].y];
            r8[u*4+3] = p[ad[u].y+1];
        }
    };
    auto sts_q = [&](int q, int buf, const float* r8) {
        float v0 = wq[0].x*r8[0] + wq[0].y*r8[1] + wq[0].z*r8[2] + wq[0].w*r8[3];
        float v1 = wq[1].x*r8[4] + wq[1].y*r8[5] + wq[1].z*r8[6] + wq[1].w*r8[7];
        __nv_bfloat162 hh = __floats2bfloat162_rn(v0, v1);
        float l0 = v0 - __bfloat162float(hh.x);
        float l1 = v1 - __bfloat162float(hh.y);
        __nv_bfloat162 ll = __floats2bfloat162_rn(l0, l1);
        uint32_t so = rowb + (((uint32_t)(q * 32 + grpT * 4)) ^ xorv);
        *(uint32_t*)(smem + OFF_B + (buf*2 + 0) * 8192 + so) = *(uint32_t*)&hh;
        *(uint32_t*)(smem + OFF_B + (buf*2 + 1) * 8192 + so) = *(uint32_t*)&ll;
    };

    // ---- conv gather: all 8 LDG up front (one latency exposure), sts split in halves ----
    auto ldg_conv = [&](int c, float* r8) {
        int hw = hw0 + pxT;
        int h = hw / WOUT, w_ = hw - h * WOUT;
        int k0 = c * KC + grpT * 8;
#pragma unroll
        for (int t = 0; t < 8; t++) {
            int k = k0 + t;
            int ci = k / 9, jj = k - ci * 9;
            int y  = h + jj / 3 - 1;
            int xx = w_ + (jj - (jj / 3) * 3) - 1;
            r8[t] = (y >= 0 && y < Hin && xx >= 0 && xx < Win)
                 ? __ldcg(&xb[(size_t)ci * HWin + y * Win + xx]) : 0.f;
        }
    };
    auto sts_conv = [&](int buf, const float* r8, int half) {
#pragma unroll
        for (int q = half * 2; q < half * 2 + 2; q++) {
            __nv_bfloat162 hh = __floats2bfloat162_rn(r8[q*2], r8[q*2+1]);
            float l0 = r8[q*2]   - __bfloat162float(hh.x);
            float l1 = r8[q*2+1] - __bfloat162float(hh.y);
            __nv_bfloat162 ll = __floats2bfloat162_rn(l0, l1);
            uint32_t so = rowb + (((uint32_t)(grpT * 16 + q * 4)) ^ xorv);
            *(uint32_t*)(smem + OFF_B + (buf*2 + 0) * 8192 + so) = *(uint32_t*)&hh;
            *(uint32_t*)(smem + OFF_B + (buf*2 + 1) * 8192 + so) = *(uint32_t*)&ll;
        }
    };

    const uint32_t aOff = (uint32_t)((m0w + (lid & 15)) * 128 + (lid >> 4) * 16);
    const uint32_t bOff = (uint32_t)((n0w + (lid & 7) + ((lid >> 4) & 1) * 8) * 128 + ((lid >> 3) & 1) * 16);

    // one ks-group of MMAs on buffer `buf`
    auto mma_ks = [&](int buf, int ks) {
        const uint32_t sAh = sb + (uint32_t)((buf*2 + 0) * ABUF);
        const uint32_t sAl = sb + (uint32_t)((buf*2 + 1) * ABUF);
        const uint32_t sBh = sb + OFF_B + (buf*2 + 0) * 8192;
        const uint32_t sBl = sb + OFF_B + (buf*2 + 1) * 8192;
        uint32_t bh[4], bl[4];
        ldsm4(bh, sBh + sw128(bOff + (uint32_t)(ks * 32)));
        ldsm4(bl, sBl + sw128(bOff + (uint32_t)(ks * 32)));
#pragma unroll
        for (int i = 0; i < MT; i++) {
            uint32_t ah[4], al[4];
            ldsm4(ah, sAh + sw128(aOff + (uint32_t)(i * 2048 + ks * 32)));
            ldsm4(al, sAl + sw128(aOff + (uint32_t)(i * 2048 + ks * 32)));
#pragma unroll
            for (int jn = 0; jn < 2; jn++) {
                int sel = jn * 2;
                mma16816(acc[i][jn], ah, bh[sel], bh[sel + 1]);
                mma16816(acc[i][jn], ah, bl[sel], bl[sel + 1]);
                mma16816(acc[i][jn], al, bh[sel], bh[sel + 1]);
            }
        }
    };

    // ---- prologue: chunk 0 ----
    loadA_async(0, 0);
    if (MODE == 1) {
        float r8[8];
#pragma unroll
        for (int q = 0; q < 4; q++) { ldg_q(0, q, r8); sts_q(q, 0, r8); }
    } else {
        float r8[8];
        ldg_conv(0, r8);
        sts_conv(0, r8, 0);
        sts_conv(0, r8, 1);
    }
    asm volatile("cp.async.wait_group 0;");
    __syncthreads();

    // ---- mainloop ----
    if (MODE == 1) {
        float r0[8], r1[8];
        for (int c = 0; c < NC; c++) {
            const int buf = c & 1;
            const bool nxt = (c + 1 < NC);
            if (nxt) {
                loadA_async(c + 1, buf ^ 1);
                ldg_q(c + 1, 0, r0);
                ldg_q(c + 1, 1, r1);
            }
            mma_ks(buf, 0);
            if (nxt) { sts_q(0, buf ^ 1, r0); ldg_q(c + 1, 2, r0); }
            mma_ks(buf, 1);
            if (nxt) { sts_q(1, buf ^ 1, r1); ldg_q(c + 1, 3, r1); }
            mma_ks(buf, 2);
            if (nxt) sts_q(2, buf ^ 1, r0);
            mma_ks(buf, 3);
            if (nxt) {
                sts_q(3, buf ^ 1, r1);
                asm volatile("cp.async.wait_group 0;");
            }
            __syncthreads();
        }
    } else {
        float r8[8];
        for (int c = 0; c < NC; c++) {
            const int buf = c & 1;
            const bool nxt = (c + 1 < NC);
            if (nxt) {
                loadA_async(c + 1, buf ^ 1);
                ldg_conv(c + 1, r8);   // all 8 LDGs in flight through the MMA phase
            }
            mma_ks(buf, 0);
            mma_ks(buf, 1);
            if (nxt) sts_conv(buf ^ 1, r8, 0);
            mma_ks(buf, 2);
            mma_ks(buf, 3);
            if (nxt) {
                sts_conv(buf ^ 1, r8, 1);
                asm volatile("cp.async.wait_group 0;");
            }
            __syncthreads();
        }
    }

    // ---- epilogue ----
#pragma unroll
    for (int i = 0; i < MT; i++) {
        int row0 = m0w + i * 16 + (lid >> 2);
#pragma unroll
        for (int half = 0; half < 2; half++) {
            int co = row0 + half * 8;
            if (co >= Cout) continue;
            float bv = bias[co];
#pragma unroll
            for (int jn = 0; jn < 2; jn++) {
                float v0 = acc[i][jn][half * 2 + 0] + bv;
                float v1 = acc[i][jn][half * 2 + 1] + bv;
                if (EPI == 3) {
                    int cb = co * 64 + n0w + (lid & 3) * 2 + jn * 8;
                    som[cb] = v0; som[cb + 1] = v1;
                } else {
                    size_t o = ((size_t)b * Cout + co) * HWOUT + hw0 + n0w + (lid & 3) * 2 + jn * 8;
                    if (EPI == 1) {
                        float2 s = __ldcg((const float2*)(epi_src + o));
                        v0 = fmaxf(v0, 0.f) + s.x; v1 = fmaxf(v1, 0.f) + s.y;
                    } else if (EPI == 2) {
                        float2 s = __ldcg((const float2*)(epi_src + o));
                        v0 += s.x; v1 += s.y;
                    }
                    *(float2*)(out + o) = make_float2(v0, v1);
                }
            }
        }
    }
}

__global__ void __launch_bounds__(NTHREADS)
dcnfpn_persist(const float* __restrict__ f0, const float* __restrict__ f1,
               const float* __restrict__ f2,
               const float* cw0, const float* cb0, const float* cw1, const float* cb1,
               const float* dw0, const float* db0, const float* dw1, const float* db1,
               const float* rw, const float* rb, float* __restrict__ out)
{
    extern __shared__ __align__(1024) char smem[];
    const int bx = blockIdx.x;
    const int tid = threadIdx.x;
    const int gtid = bx * NTHREADS + tid;
    const int GT = GRID * NTHREADS;

    // ---- prep: weights fp32 -> bf16 hi/lo; gf = f2 ----
    {
        const float* dsrc[2] = {dw0, dw1};
        for (int l = 0; l < 2; l++) {
            __nv_bfloat16* hi = g_wdef + (size_t)l * 2 * ND;
            __nv_bfloat16* lo = hi + ND;
            for (int i = gtid; i < ND; i += GT) {
                float v = dsrc[l][i];
                __nv_bfloat16 h = __float2bfloat16(v);
                hi[i] = h; lo[i] = __float2bfloat16(v - __bfloat162float(h));
            }
        }
        const float* csrc[2] = {cw0, cw1};
        for (int l = 0; l < 2; l++) {
            __nv_bfloat16* hi = g_wcom + (size_t)l * 2 * NCOM;
            __nv_bfloat16* lo = hi + NCOM;
            for (int i = gtid; i < NCOM; i += GT) {
                int row = i / KCONV;
                float v = (row < 48) ? csrc[l][i] : 0.f;
                __nv_bfloat16 h = __float2bfloat16(v);
                hi[i] = h; lo[i] = __float2bfloat16(v - __bfloat162float(h));
            }
        }
        for (int i = gtid; i < NRES; i += GT) {
            float v = rw[i];
            __nv_bfloat16 h = __float2bfloat16(v);
            g_wres[i] = h; g_wres[NRES + i] = __float2bfloat16(v - __bfloat162float(h));
        }
        const float4* s4 = (const float4*)f2;
        float4* d4 = (float4*)g_f;
        for (int i = gtid; i < BATCH*CIN*HWOUT/4; i += GT) d4[i] = s4[i];
    }
    grid_bar(0);

    float* som = (float*)(smem + OFF_OM);
    const float* feats[2] = {f1, f0};
    const float* cb[2] = {cb0, cb1};
    const float* db[2] = {db0, db1};
    const int Hins[2] = {80, 160};
    const int strides[2] = {2, 4};
    const int pads[2] = {1, 3};
    const int dils[2] = {1, 3};

    int slot = 1;
    for (int rep = 0; rep < 2; rep++) {
        for (int l = 0; l < 2; l++) {
            stage_gemm<0,3,1>(smem, bx, g_f, 40, 40,
                g_wcom + (size_t)l*2*NCOM, g_wcom + (size_t)l*2*NCOM + NCOM,
                cb[l], som, nullptr, nullptr, 48, KCONV, 1, 1, 1);
            stage_gemm<1,1,4>(smem, bx, feats[l], Hins[l], Hins[l],
                g_wdef + (size_t)l*2*ND, g_wdef + (size_t)l*2*ND + ND,
                db[l], som, g_f, g_f, 256, KDEF, strides[l], pads[l], dils[l]);
            grid_bar(slot++);
        }
    }
    stage_gemm<0,2,4>(smem, bx, g_f, 40, 40,
        g_wres, g_wres + NRES, rb, nullptr, f2, out, 256, KCONV, 1, 1, 1);
}

extern "C" void kernel_launch(void* const* d_in, const int* in_sizes, int n_in,
                              void* d_out, int out_size)
{
    const float* f0 = (const float*)d_in[0];
    const float* f1 = (const float*)d_in[1];
    const float* f2 = (const float*)d_in[2];

    cudaFuncSetAttribute(dcnfpn_persist, cudaFuncAttributeMaxDynamicSharedMemorySize, SMEM_TOTAL);

    dcnfpn_persist<<<GRID, NTHREADS, SMEM_TOTAL>>>(
        f0, f1, f2,
        (const float*)d_in[3], (const float*)d_in[4],
        (const float*)d_in[5], (const float*)d_in[6],
        (const float*)d_in[7], (const float*)d_in[8],
        (const float*)d_in[9], (const float*)d_in[10],
        (const float*)d_in[11], (const float*)d_in[12],
        (float*)d_out);
}

// round 15
// speedup vs baseline: 1.3502x; 1.0258x over previous
#include <cuda_runtime.h>
#include <cuda_bf16.h>
#include <math.h>
#include <stdint.h>

#define WOUT 40
#define HWOUT 1600
#define CIN 256
#define BATCH 4

#define BN 64
#define KC 64
#define NTHREADS 512
#define GRID 100
#define KDEF (CIN*16)
#define KCONV (CIN*9)

#define ND (256*KDEF)
#define NCOM (64*KCONV)
#define NRES (256*KCONV)

// smem (bytes): A [0,131072) B [131072,163840) OM [163840,176128) MBAR [176128,176192)
#define OFF_OM 163840
#define OFF_MBAR 176128
#define SMEM_TOTAL 176192

__device__ float g_f[BATCH*CIN*HWOUT];
// weights stored as the pre-swizzled smem image: per (layer) chunk-major
// blocks of (c*2+fmt)*ABUF, ABUF = BM*128 bytes, sw128 applied at prep time.
__device__ __align__(16) __nv_bfloat16 g_wdef[2*2*ND];
__device__ __align__(16) __nv_bfloat16 g_wcom[2*2*NCOM];
__device__ __align__(16) __nv_bfloat16 g_wres[2*NRES];
__device__ unsigned int g_cnt[8];

__device__ __forceinline__ uint32_t smem_u32(const void* p) {
    uint32_t a;
    asm("{ .reg .u64 t; cvta.to.shared.u64 t, %1; cvt.u32.u64 %0, t; }" : "=r"(a) : "l"(p));
    return a;
}
__device__ __forceinline__ uint32_t sw128(uint32_t o) { return o ^ ((o >> 3) & 0x70); }

__device__ __forceinline__ void ldsm4(uint32_t* r, uint32_t addr) {
    asm volatile("ldmatrix.sync.aligned.m8n8.x4.shared.b16 {%0,%1,%2,%3}, [%4];"
        : "=r"(r[0]), "=r"(r[1]), "=r"(r[2]), "=r"(r[3]) : "r"(addr));
}
__device__ __forceinline__ void mma16816(float* c, const uint32_t* a, uint32_t b0, uint32_t b1) {
    asm volatile("mma.sync.aligned.m16n8k16.row.col.f32.bf16.bf16.f32 "
        "{%0,%1,%2,%3},{%4,%5,%6,%7},{%8,%9},{%0,%1,%2,%3};"
        : "+f"(c[0]), "+f"(c[1]), "+f"(c[2]), "+f"(c[3])
        : "r"(a[0]), "r"(a[1]), "r"(a[2]), "r"(a[3]), "r"(b0), "r"(b1));
}

#define MBAR_INIT(a, n) asm volatile("mbarrier.init.shared.b64 [%0], %1;" :: "r"(a), "r"(n) : "memory")
#define MBAR_EXPECT_TX(a, bytes) \
    asm volatile("mbarrier.arrive.expect_tx.shared.b64 _, [%0], %1;" :: "r"(a), "r"(bytes) : "memory")
#define BULK_G2S(dst, src, size, mbar) \
    asm volatile("cp.async.bulk.shared::cta.global.mbarrier::complete_tx::bytes [%0], [%1], %2, [%3];" \
        :: "r"(dst), "l"(src), "r"(size), "r"(mbar) : "memory")
#define MBAR_WAIT(addr, par) do { \
    uint32_t _m = (addr); uint32_t _p = (uint32_t)(par); uint32_t _d; \
    asm volatile("{\n\t.reg .pred p;\n\tmbarrier.try_wait.parity.acquire.cta.shared::cta.b64 p, [%1], %2;\n\tselp.b32 %0, 1, 0, p;\n\t}" \
        : "=r"(_d) : "r"(_m), "r"(_p) : "memory"); \
    if (!_d) { \
        asm volatile("{\n\t.reg .pred P1;\n\tWL_%=:\n\tmbarrier.try_wait.parity.acquire.cta.shared::cta.b64 P1, [%0], %1, 0x989680;\n\t@P1 bra.uni WD_%=;\n\tbra.uni WL_%=;\n\tWD_%=:\n\t}" \
            :: "r"(_m), "r"(_p) : "memory"); } \
} while(0)

// monotone-counter grid barrier (graph-replay safe)
__device__ __forceinline__ void grid_bar(int slot) {
    __syncthreads();
    if (threadIdx.x == 0) {
        __threadfence();
        unsigned int old = atomicAdd(&g_cnt[slot], 1u);
        unsigned int target = (old / GRID) * GRID + GRID;
        while (*(volatile unsigned int*)&g_cnt[slot] < target) __nanosleep(64);
    }
    __syncthreads();
}

// MODE 0: implicit 3x3 conv (s1 p1; x = mutable gf, read via __ldcg).
// MODE 1: modulated deform conv (k=4,K=16), meta from smem om; x = immutable feat.
// EPI 0:+bias 1:relu(v+b)+__ldcg(epi) 2:v+b+__ldcg(epi) 3:+bias->som
// wblk: pre-swizzled weight image, (chunk*2+fmt)*ABUF blocks.
template<int MODE, int EPI, int MT>
__device__ void stage_gemm(char* smem, int bx,
        const float* __restrict__ x, int Hin, int Win,
        const char* __restrict__ wblk, const float* __restrict__ bias,
        float* som, const float* __restrict__ epi_src, float* __restrict__ out,
        int Cout, int Ktot, int stride, int pad, int dil, int* ph)
{
    constexpr int BM = MT * 64;
    constexpr int ABUF = BM * 128;
    constexpr int OFF_B = 4 * ABUF;

    const uint32_t sb = smem_u32(smem);
    const int tid = threadIdx.x;
    const int wid = tid >> 5, lid = tid & 31;
    const int n0 = bx * BN;
    const int b  = n0 / HWOUT;
    const int hw0 = n0 - b * HWOUT;
    const int HWin = Hin * Win;
    const float* xb = x + (size_t)b * CIN * HWin;

    __syncthreads();   // previous stage fully done with smem

    const int pxT = tid & 63;
    const int grpT = tid >> 6;
    const uint32_t xorv = (uint32_t)((pxT & 7) << 4);
    const uint32_t rowb = (uint32_t)(pxT * 128);

    // ---- per-thread deform meta (tap pair) from smem om, held in regs ----
    int2 ad[2]; float4 wq[2];
    if (MODE == 1) {
#pragma unroll
        for (int u = 0; u < 2; u++) {
            int k = 2 * grpT + u;
            int hw = hw0 + pxT;
            int h = hw / WOUT, w = hw - h * WOUT;
            float dy = som[(2*k  ) * 64 + pxT];
            float dx = som[(2*k+1) * 64 + pxT];
            float mm = som[(32+k ) * 64 + pxT];
            mm = 1.0f / (1.0f + expf(-mm));
            float py = (float)((k >> 2) * dil + h * stride - pad) + dy;
            float px = (float)((k &  3) * dil + w * stride - pad) + dx;
            float fy = floorf(py), fx = floorf(px);
            int y0 = (int)fy, x0 = (int)fx;
            int y1 = y0 + 1, x1 = x0 + 1;
            float ly = py - fy, lx = px - fx;
            float wy0 = ((y0 >= 0) & (y0 < Hin)) ? (1.f - ly) * mm : 0.f;
            float wy1 = ((y1 >= 0) & (y1 < Hin)) ? ly * mm : 0.f;
            float wx0 = ((x0 >= 0) & (x0 < Win)) ? (1.f - lx) : 0.f;
            float wx1 = ((x1 >= 0) & (x1 < Win)) ? lx : 0.f;
            int xL = min(max(x0, 0), Win - 2);
            float wL = (x0 == xL ? wx0 : 0.f) + (x1 == xL ? wx1 : 0.f);
            float wR = (x0 == xL + 1 ? wx0 : 0.f) + (x1 == xL + 1 ? wx1 : 0.f);
            int yT = min(max(y0, 0), Hin - 1);
            int yB = min(max(y1, 0), Hin - 1);
            ad[u] = make_int2(yT * Win + xL, (yB - yT) * Win);
            wq[u] = make_float4(wy0 * wL, wy0 * wR, wy1 * wL, wy1 * wR);
        }
    }

    float acc[MT][2][4];
#pragma unroll
    for (int i = 0; i < MT; i++)
#pragma unroll
        for (int j = 0; j < 2; j++)
#pragma unroll
            for (int q = 0; q < 4; q++) acc[i][j][q] = 0.f;

    const int NC = Ktot / KC;
    const int wm = wid & 3, wn = wid >> 2;
    const int m0w = wm * (MT * 16);
    const int n0w = wn * 16;

    // ---- A tile: 2 bulk copies of the pre-swizzled image (1 thread) ----
    auto loadA_bulk = [&](int c, int buf) {
        if (tid == 0) {
            uint32_t mb = sb + OFF_MBAR + buf * 8;
            asm volatile("fence.proxy.async.shared::cta;" ::: "memory");
            MBAR_EXPECT_TX(mb, (uint32_t)(2 * ABUF));
            BULK_G2S(sb + (uint32_t)((buf*2 + 0) * ABUF),
                     wblk + (size_t)(c*2 + 0) * ABUF, (uint32_t)ABUF, mb);
            BULK_G2S(sb + (uint32_t)((buf*2 + 1) * ABUF),
                     wblk + (size_t)(c*2 + 1) * ABUF, (uint32_t)ABUF, mb);
        }
    };
    auto waitA = [&](int buf) {
        uint32_t mb = sb + OFF_MBAR + buf * 8;
        MBAR_WAIT(mb, ph[buf]);
        ph[buf] ^= 1;
    };

    // ---- deform gather, quarter granularity ----
    auto ldg_q = [&](int c, int q, float* r8) {
        const float* plane = xb + (size_t)(c * 4 + q) * HWin;
#pragma unroll
        for (int u = 0; u < 2; u++) {
            const float* p = plane + ad[u].x;
            r8[u*4+0] = p[0];
            r8[u*4+1] = p[1];
            r8[u*4+2] = p[ad[u].y];
            r8[u*4+3] = p[ad[u].y+1];
        }
    };
    auto sts_q = [&](int q, int buf, const float* r8) {
        float v0 = wq[0].x*r8[0] + wq[0].y*r8[1] + wq[0].z*r8[2] + wq[0].w*r8[3];
        float v1 = wq[1].x*r8[4] + wq[1].y*r8[5] + wq[1].z*r8[6] + wq[1].w*r8[7];
        __nv_bfloat162 hh = __floats2bfloat162_rn(v0, v1);
        float l0 = v0 - __bfloat162float(hh.x);
        float l1 = v1 - __bfloat162float(hh.y);
        __nv_bfloat162 ll = __floats2bfloat162_rn(l0, l1);
        uint32_t so = rowb + (((uint32_t)(q * 32 + grpT * 4)) ^ xorv);
        *(uint32_t*)(smem + OFF_B + (buf*2 + 0) * 8192 + so) = *(uint32_t*)&hh;
        *(uint32_t*)(smem + OFF_B + (buf*2 + 1) * 8192 + so) = *(uint32_t*)&ll;
    };

    // ---- conv gather ----
    auto ldg_conv = [&](int c, float* r8) {
        int hw = hw0 + pxT;
        int h = hw / WOUT, w_ = hw - h * WOUT;
        int k0 = c * KC + grpT * 8;
#pragma unroll
        for (int t = 0; t < 8; t++) {
            int k = k0 + t;
            int ci = k / 9, jj = k - ci * 9;
            int y  = h + jj / 3 - 1;
            int xx = w_ + (jj - (jj / 3) * 3) - 1;
            r8[t] = (y >= 0 && y < Hin && xx >= 0 && xx < Win)
                 ? __ldcg(&xb[(size_t)ci * HWin + y * Win + xx]) : 0.f;
        }
    };
    auto sts_conv = [&](int buf, const float* r8, int half) {
#pragma unroll
        for (int q = half * 2; q < half * 2 + 2; q++) {
            __nv_bfloat162 hh = __floats2bfloat162_rn(r8[q*2], r8[q*2+1]);
            float l0 = r8[q*2]   - __bfloat162float(hh.x);
            float l1 = r8[q*2+1] - __bfloat162float(hh.y);
            __nv_bfloat162 ll = __floats2bfloat162_rn(l0, l1);
            uint32_t so = rowb + (((uint32_t)(grpT * 16 + q * 4)) ^ xorv);
            *(uint32_t*)(smem + OFF_B + (buf*2 + 0) * 8192 + so) = *(uint32_t*)&hh;
            *(uint32_t*)(smem + OFF_B + (buf*2 + 1) * 8192 + so) = *(uint32_t*)&ll;
        }
    };

    const uint32_t aOff = (uint32_t)((m0w + (lid & 15)) * 128 + (lid >> 4) * 16);
    const uint32_t bOff = (uint32_t)((n0w + (lid & 7) + ((lid >> 4) & 1) * 8) * 128 + ((lid >> 3) & 1) * 16);

    auto mma_ks = [&](int buf, int ks) {
        const uint32_t sAh = sb + (uint32_t)((buf*2 + 0) * ABUF);
        const uint32_t sAl = sb + (uint32_t)((buf*2 + 1) * ABUF);
        const uint32_t sBh = sb + OFF_B + (buf*2 + 0) * 8192;
        const uint32_t sBl = sb + OFF_B + (buf*2 + 1) * 8192;
        uint32_t bh[4], bl[4];
        ldsm4(bh, sBh + sw128(bOff + (uint32_t)(ks * 32)));
        ldsm4(bl, sBl + sw128(bOff + (uint32_t)(ks * 32)));
#pragma unroll
        for (int i = 0; i < MT; i++) {
            uint32_t ah[4], al[4];
            ldsm4(ah, sAh + sw128(aOff + (uint32_t)(i * 2048 + ks * 32)));
            ldsm4(al, sAl + sw128(aOff + (uint32_t)(i * 2048 + ks * 32)));
#pragma unroll
            for (int jn = 0; jn < 2; jn++) {
                int sel = jn * 2;
                mma16816(acc[i][jn], ah, bh[sel], bh[sel + 1]);
                mma16816(acc[i][jn], ah, bl[sel], bl[sel + 1]);
                mma16816(acc[i][jn], al, bh[sel], bh[sel + 1]);
            }
        }
    };

    // ---- prologue: chunk 0 ----
    loadA_bulk(0, 0);
    if (MODE == 1) {
        float r8[8];
#pragma unroll
        for (int q = 0; q < 4; q++) { ldg_q(0, q, r8); sts_q(q, 0, r8); }
    } else {
        float r8[8];
        ldg_conv(0, r8);
        sts_conv(0, r8, 0);
        sts_conv(0, r8, 1);
    }
    waitA(0);
    __syncthreads();

    // ---- mainloop ----
    if (MODE == 1) {
        float r0[8], r1[8];
        for (int c = 0; c < NC; c++) {
            const int buf = c & 1;
            const bool nxt = (c + 1 < NC);
            if (nxt) {
                loadA_bulk(c + 1, buf ^ 1);
                ldg_q(c + 1, 0, r0);
                ldg_q(c + 1, 1, r1);
            }
            mma_ks(buf, 0);
            if (nxt) { sts_q(0, buf ^ 1, r0); ldg_q(c + 1, 2, r0); }
            mma_ks(buf, 1);
            if (nxt) { sts_q(1, buf ^ 1, r1); ldg_q(c + 1, 3, r1); }
            mma_ks(buf, 2);
            if (nxt) sts_q(2, buf ^ 1, r0);
            mma_ks(buf, 3);
            if (nxt) {
                sts_q(3, buf ^ 1, r1);
                waitA(buf ^ 1);
            }
            __syncthreads();
        }
    } else {
        float r8[8];
        for (int c = 0; c < NC; c++) {
            const int buf = c & 1;
            const bool nxt = (c + 1 < NC);
            if (nxt) {
                loadA_bulk(c + 1, buf ^ 1);
                ldg_conv(c + 1, r8);
            }
            mma_ks(buf, 0);
            mma_ks(buf, 1);
            if (nxt) sts_conv(buf ^ 1, r8, 0);
            mma_ks(buf, 2);
            mma_ks(buf, 3);
            if (nxt) {
                sts_conv(buf ^ 1, r8, 1);
                waitA(buf ^ 1);
            }
            __syncthreads();
        }
    }

    // ---- epilogue ----
#pragma unroll
    for (int i = 0; i < MT; i++) {
        int row0 = m0w + i * 16 + (lid >> 2);
#pragma unroll
        for (int half = 0; half < 2; half++) {
            int co = row0 + half * 8;
            if (co >= Cout) continue;
            float bv = bias[co];
#pragma unroll
            for (int jn = 0; jn < 2; jn++) {
                float v0 = acc[i][jn][half * 2 + 0] + bv;
                float v1 = acc[i][jn][half * 2 + 1] + bv;
                if (EPI == 3) {
                    int cb = co * 64 + n0w + (lid & 3) * 2 + jn * 8;
                    som[cb] = v0; som[cb + 1] = v1;
                } else {
                    size_t o = ((size_t)b * Cout + co) * HWOUT + hw0 + n0w + (lid & 3) * 2 + jn * 8;
                    if (EPI == 1) {
                        float2 s = __ldcg((const float2*)(epi_src + o));
                        v0 = fmaxf(v0, 0.f) + s.x; v1 = fmaxf(v1, 0.f) + s.y;
                    } else if (EPI == 2) {
                        float2 s = __ldcg((const float2*)(epi_src + o));
                        v0 += s.x; v1 += s.y;
                    }
                    *(float2*)(out + o) = make_float2(v0, v1);
                }
            }
        }
    }
}

__global__ void __launch_bounds__(NTHREADS)
dcnfpn_persist(const float* __restrict__ f0, const float* __restrict__ f1,
               const float* __restrict__ f2,
               const float* cw0, const float* cb0, const float* cw1, const float* cb1,
               const float* dw0, const float* db0, const float* dw1, const float* db1,
               const float* rw, const float* rb, float* __restrict__ out)
{
    extern __shared__ __align__(1024) char smem[];
    const int bx = blockIdx.x;
    const int tid = threadIdx.x;
    const int gtid = bx * NTHREADS + tid;
    const int GT = GRID * NTHREADS;
    const uint32_t sb = smem_u32(smem);

    if (tid == 0) {
        MBAR_INIT(sb + OFF_MBAR, 1);
        MBAR_INIT(sb + OFF_MBAR + 8, 1);
    }

    // ---- prep: weights fp32 -> bf16 hi/lo into the pre-swizzled smem image ----
    {
        const float* dsrc[2] = {dw0, dw1};
        for (int l = 0; l < 2; l++) {
            char* base = (char*)g_wdef + (size_t)l * 2 * ND * 2;
            for (int i = gtid; i < ND; i += GT) {
                int r = i >> 12, k = i & 4095;              // KDEF = 4096
                int c = k >> 6, j = (k >> 3) & 7, t = k & 7;
                float v = dsrc[l][i];
                __nv_bfloat16 hbf = __float2bfloat16(v);
                __nv_bfloat16 lbf = __float2bfloat16(v - __bfloat162float(hbf));
                uint32_t off = (uint32_t)((c * 2) * 32768) + sw128((uint32_t)(r*128 + j*16)) + t*2;
                *(__nv_bfloat16*)(base + off)         = hbf;
                *(__nv_bfloat16*)(base + off + 32768) = lbf;
            }
        }
        const float* csrc[2] = {cw0, cw1};
        for (int l = 0; l < 2; l++) {
            char* base = (char*)g_wcom + (size_t)l * 2 * NCOM * 2;
            for (int i = gtid; i < NCOM; i += GT) {
                int r = i / KCONV, k = i - r * KCONV;
                int c = k >> 6, j = (k >> 3) & 7, t = k & 7;
                float v = (r < 48) ? csrc[l][i] : 0.f;
                __nv_bfloat16 hbf = __float2bfloat16(v);
                __nv_bfloat16 lbf = __float2bfloat16(v - __bfloat162float(hbf));
                uint32_t off = (uint32_t)((c * 2) * 8192) + sw128((uint32_t)(r*128 + j*16)) + t*2;
                *(__nv_bfloat16*)(base + off)        = hbf;
                *(__nv_bfloat16*)(base + off + 8192) = lbf;
            }
        }
        {
            char* base = (char*)g_wres;
            for (int i = gtid; i < NRES; i += GT) {
                int r = i / KCONV, k = i - r * KCONV;
                int c = k >> 6, j = (k >> 3) & 7, t = k & 7;
                float v = rw[i];
                __nv_bfloat16 hbf = __float2bfloat16(v);
                __nv_bfloat16 lbf = __float2bfloat16(v - __bfloat162float(hbf));
                uint32_t off = (uint32_t)((c * 2) * 32768) + sw128((uint32_t)(r*128 + j*16)) + t*2;
                *(__nv_bfloat16*)(base + off)         = hbf;
                *(__nv_bfloat16*)(base + off + 32768) = lbf;
            }
        }
        const float4* s4 = (const float4*)f2;
        float4* d4 = (float4*)g_f;
        for (int i = gtid; i < BATCH*CIN*HWOUT/4; i += GT) d4[i] = s4[i];
    }
    grid_bar(0);

    float* som = (float*)(smem + OFF_OM);
    const float* feats[2] = {f1, f0};
    const float* cb[2] = {cb0, cb1};
    const float* db[2] = {db0, db1};
    const int Hins[2] = {80, 160};
    const int strides[2] = {2, 4};
    const int pads[2] = {1, 3};
    const int dils[2] = {1, 3};
    int ph[2] = {0, 0};

    int slot = 1;
    for (int rep = 0; rep < 2; rep++) {
        for (int l = 0; l < 2; l++) {
            stage_gemm<0,3,1>(smem, bx, g_f, 40, 40,
                (const char*)g_wcom + (size_t)l*2*NCOM*2,
                cb[l], som, nullptr, nullptr, 48, KCONV, 1, 1, 1, ph);
            stage_gemm<1,1,4>(smem, bx, feats[l], Hins[l], Hins[l],
                (const char*)g_wdef + (size_t)l*2*ND*2,
                db[l], som, g_f, g_f, 256, KDEF, strides[l], pads[l], dils[l], ph);
            grid_bar(slot++);
        }
    }
    stage_gemm<0,2,4>(smem, bx, g_f, 40, 40,
        (const char*)g_wres, rb, nullptr, f2, out, 256, KCONV, 1, 1, 1, ph);
}

extern "C" void kernel_launch(void* const* d_in, const int* in_sizes, int n_in,
                              void* d_out, int out_size)
{
    const float* f0 = (const float*)d_in[0];
    const float* f1 = (const float*)d_in[1];
    const float* f2 = (const float*)d_in[2];

    cudaFuncSetAttribute(dcnfpn_persist, cudaFuncAttributeMaxDynamicSharedMemorySize, SMEM_TOTAL);

    dcnfpn_persist<<<GRID, NTHREADS, SMEM_TOTAL>>>(
        f0, f1, f2,
        (const float*)d_in[3], (const float*)d_in[4],
        (const float*)d_in[5], (const float*)d_in[6],
        (const float*)d_in[7], (const float*)d_in[8],
        (const float*)d_in[9], (const float*)d_in[10],
        (const float*)d_in[11], (const float*)d_in[12],
        (float*)d_out);
}